// round 3
// baseline (speedup 1.0000x reference)
#include <cuda_runtime.h>
#include <cstdint>

// Problem constants (BATCH=4, SEQ=4096, DIM=1024)
#define B 4
#define L 4096
#define D 1024
#define C  32                  // chunk length (timesteps per block)
#define NC 128                 // chunks along L  (NC*C == L)
#define LOG2C 5
#define HALves 2               // dim halves (512 dims per block)
#define NTHREADS 512

// Scratch (__device__ globals: allocation-free rule)
__device__ float2 g_T[B * NC * D];        // chunk aggregates (end state, zero-init scan)
__device__ float2 g_I[B * NC * D];        // inclusive prefixes (exact end state)
__device__ int    g_flag[B * NC * HALves]; // 0=none, 1=aggregate, 2=prefix

__device__ __forceinline__ float2 cmul(float2 u, float2 v) {
    return make_float2(fmaf(u.x, v.x, -u.y * v.y), fmaf(u.x, v.y, u.y * v.x));
}

__device__ __forceinline__ float2 decay(float r, float im) {
    float mag = sqrtf(fmaf(r, r, im * im));
    float s = __expf(-mag) / mag;
    return make_float2(r * s, im * s);
}

__global__ void k_reset_flags() {
    int i = blockIdx.x * blockDim.x + threadIdx.x;
    if (i < B * NC * HALves) g_flag[i] = 0;
}

__global__ void __launch_bounds__(NTHREADS, 2)
spiral_lookback(const float* __restrict__ x,
                const float* __restrict__ pr, const float* __restrict__ pi,
                const float* __restrict__ ir, const float* __restrict__ ii,
                const float* __restrict__ lr, const float* __restrict__ li,
                float* __restrict__ out)
{
    const int s     = blockIdx.x;          // 0..7 : (b, half)
    const int b     = s >> 1;
    const int half  = s & 1;
    const int chunk = blockIdx.y;          // slow-varying => predecessors have lower bid
    const int d     = half * (D / 2) + threadIdx.x;
    const int lane  = threadIdx.x & 31;

    const float2 a = decay(pr[d], pi[d]);
    const float cr = ir[d], ci = ii[d];

    const float* xp = x + ((size_t)(b * L + chunk * C)) * D + d;
    float* op = out + ((size_t)(b * L + chunk * C)) * D + d;

    // ---- Phase 1: zero-init local scan, Re kept in registers ----
    float hre[C];
    float hr = 0.f, hi = 0.f;
#pragma unroll
    for (int t = 0; t < C; t++) {
        float xv = __ldg(xp + (size_t)t * D);
        float nr = fmaf(a.x, hr, fmaf(-a.y, hi, cr * xv));
        float ni = fmaf(a.x, hi, fmaf( a.y, hr, ci * xv));
        hr = nr; hi = ni;
        hre[t] = hr;
    }

    const size_t myidx = ((size_t)b * NC + chunk) * D + d;
    g_T[myidx] = make_float2(hr, hi);
    __threadfence();
    __syncthreads();
    const int myflag = (b * NC + chunk) * HALves + half;
    if (threadIdx.x == 0) g_flag[myflag] = 1;   // aggregate available

    // a^C via repeated squaring
    float2 aC = a;
#pragma unroll
    for (int k = 0; k < LOG2C; k++) aC = cmul(aC, aC);

    // ---- Decoupled look-back: E = exact state entering this chunk ----
    float Er = 0.f, Ei = 0.f;
    float2 w = make_float2(1.f, 0.f);
    bool found_prefix = false;
    for (int j = chunk - 1; j >= 0; j--) {
        const int fj = (b * NC + j) * HALves + half;
        int st;
        if (lane == 0) {
            do { st = ((volatile int*)g_flag)[fj]; } while (st == 0);
        }
        st = __shfl_sync(0xffffffffu, st, 0);
        __threadfence();
        const size_t ij = ((size_t)b * NC + j) * D + d;
        if (st == 2) {
            float2 I = g_I[ij];
            Er = fmaf(w.x, I.x, fmaf(-w.y, I.y, Er));
            Ei = fmaf(w.x, I.y, fmaf( w.y, I.x, Ei));
            found_prefix = true;
            break;
        } else {
            float2 T = g_T[ij];
            Er = fmaf(w.x, T.x, fmaf(-w.y, T.y, Er));
            Ei = fmaf(w.x, T.y, fmaf( w.y, T.x, Ei));
            w = cmul(w, aC);
        }
    }
    if (!found_prefix) {
        // reached the beginning: fold in initial state last_conv
        float Hr = lr[b * D + d], Hii = li[b * D + d];
        Er = fmaf(w.x, Hr, fmaf(-w.y, Hii, Er));
        Ei = fmaf(w.x, Hii, fmaf( w.y, Hr, Ei));
    }

    // Publish inclusive prefix: I = aC * E + T_own
    {
        float Ir = fmaf(aC.x, Er, fmaf(-aC.y, Ei, hr));
        float Iim = fmaf(aC.x, Ei, fmaf( aC.y, Er, hi));
        g_I[myidx] = make_float2(Ir, Iim);
    }
    __threadfence();
    __syncthreads();
    if (threadIdx.x == 0) g_flag[myflag] = 2;   // prefix available

    // ---- Phase 2: out[t] = hre[t] + Re(a^(t+1) * E) ----
    float2 p = a;
#pragma unroll
    for (int t = 0; t < C; t++) {
        float v = fmaf(p.x, Er, fmaf(-p.y, Ei, hre[t]));
        op[(size_t)t * D] = v;
        p = cmul(p, a);
    }
}

extern "C" void kernel_launch(void* const* d_in, const int* in_sizes, int n_in,
                              void* d_out, int out_size) {
    const float* x    = (const float*)d_in[0];
    const float* p_re = (const float*)d_in[1];
    const float* p_im = (const float*)d_in[2];
    const float* i_re = (const float*)d_in[3];
    const float* i_im = (const float*)d_in[4];
    const float* lc_r = (const float*)d_in[5];
    const float* lc_i = (const float*)d_in[6];
    float* out = (float*)d_out;

    k_reset_flags<<<1, 1024>>>();

    dim3 grid(B * HALves, NC);   // x fast (8), y = chunk slow => chunk-major bid order
    spiral_lookback<<<grid, NTHREADS>>>(x, p_re, p_im, i_re, i_im, lc_r, lc_i, out);
}

// round 4
// speedup vs baseline: 1.4715x; 1.4715x over previous
#include <cuda_runtime.h>
#include <cstdint>

// Problem constants (BATCH=4, SEQ=4096, DIM=1024)
#define B 4
#define L 4096
#define D 1024
#define C  32                 // chunk length
#define NC 128                // chunks along L (NC*C == L)
#define LOG2C 5

// Scratch (__device__ globals: allocation-free rule)
__device__ float2 g_totals[B * NC * D];   // zero-init chunk-end states
__device__ float2 g_carry [B * NC * D];   // exact state entering each chunk

__device__ __forceinline__ float2 cmul(float2 u, float2 v) {
    return make_float2(fmaf(u.x, v.x, -u.y * v.y), fmaf(u.x, v.y, u.y * v.x));
}

__device__ __forceinline__ float2 decay(float r, float im) {
    float mag = sqrtf(fmaf(r, r, im * im));
    float s = __expf(-mag) / mag;
    return make_float2(r * s, im * s);
}

// ---- K1: zero-init local chunk scans -> totals. 2 dims/thread (float2). ----
__global__ void __launch_bounds__(512)
k1_totals(const float* __restrict__ x,
          const float* __restrict__ pr, const float* __restrict__ pi,
          const float* __restrict__ ir, const float* __restrict__ ii)
{
    const int d0    = threadIdx.x * 2;
    const int chunk = blockIdx.y;
    const int b     = blockIdx.z;

    const float2 a0 = decay(pr[d0],     pi[d0]);
    const float2 a1 = decay(pr[d0 + 1], pi[d0 + 1]);
    const float c0r = ir[d0],     c0i = ii[d0];
    const float c1r = ir[d0 + 1], c1i = ii[d0 + 1];

    const float* xp = x + ((size_t)(b * L + chunk * C)) * D + d0;

    float h0r = 0.f, h0i = 0.f, h1r = 0.f, h1i = 0.f;
#pragma unroll
    for (int t = 0; t < C; t++) {
        float2 xv = *(const float2*)(xp + (size_t)t * D);
        float n0r = fmaf(a0.x, h0r, fmaf(-a0.y, h0i, c0r * xv.x));
        float n0i = fmaf(a0.x, h0i, fmaf( a0.y, h0r, c0i * xv.x));
        float n1r = fmaf(a1.x, h1r, fmaf(-a1.y, h1i, c1r * xv.y));
        float n1i = fmaf(a1.x, h1i, fmaf( a1.y, h1r, c1i * xv.y));
        h0r = n0r; h0i = n0i; h1r = n1r; h1i = n1i;
    }
    *(float4*)&g_totals[((size_t)b * NC + chunk) * D + d0] =
        make_float4(h0r, h0i, h1r, h1i);
}

// ---- K2: serial carry propagation per (b,d). 4096 threads. ----
__global__ void __launch_bounds__(512)
k2_carries(const float* __restrict__ pr, const float* __restrict__ pi,
           const float* __restrict__ lr, const float* __restrict__ li)
{
    const int idx = blockIdx.x * blockDim.x + threadIdx.x;   // 0..B*D-1
    if (idx >= B * D) return;
    const int b = idx >> 10;       // /D
    const int d = idx & (D - 1);   // %D

    float2 a = decay(pr[d], pi[d]);
    float2 aC = a;
#pragma unroll
    for (int k = 0; k < LOG2C; k++) aC = cmul(aC, aC);

    float Hr = lr[idx], Hi = li[idx];
#pragma unroll 8
    for (int i = 0; i < NC; i++) {
        const size_t j = ((size_t)b * NC + i) * D + d;
        g_carry[j] = make_float2(Hr, Hi);
        float2 T = __ldg((const float2*)&g_totals[j]);
        float nr = fmaf(aC.x, Hr, fmaf(-aC.y, Hi, T.x));
        float ni = fmaf(aC.x, Hi, fmaf( aC.y, Hr, T.y));
        Hr = nr; Hi = ni;
    }
}

// ---- K3: exact scan seeded with carry; streaming stores to out. ----
__global__ void __launch_bounds__(512)
k3_scan(const float* __restrict__ x,
        const float* __restrict__ pr, const float* __restrict__ pi,
        const float* __restrict__ ir, const float* __restrict__ ii,
        float* __restrict__ out)
{
    const int d0    = threadIdx.x * 2;
    const int chunk = blockIdx.y;
    const int b     = blockIdx.z;

    const float2 a0 = decay(pr[d0],     pi[d0]);
    const float2 a1 = decay(pr[d0 + 1], pi[d0 + 1]);
    const float c0r = ir[d0],     c0i = ii[d0];
    const float c1r = ir[d0 + 1], c1i = ii[d0 + 1];

    const size_t base = ((size_t)(b * L + chunk * C)) * D + d0;
    const float* xp = x + base;
    float* op = out + base;

    float4 h0 = *(const float4*)&g_carry[((size_t)b * NC + chunk) * D + d0];
    float h0r = h0.x, h0i = h0.y, h1r = h0.z, h1i = h0.w;

#pragma unroll
    for (int t = 0; t < C; t++) {
        float2 xv = *(const float2*)(xp + (size_t)t * D);
        float n0r = fmaf(a0.x, h0r, fmaf(-a0.y, h0i, c0r * xv.x));
        float n0i = fmaf(a0.x, h0i, fmaf( a0.y, h0r, c0i * xv.x));
        float n1r = fmaf(a1.x, h1r, fmaf(-a1.y, h1i, c1r * xv.y));
        float n1i = fmaf(a1.x, h1i, fmaf( a1.y, h1r, c1i * xv.y));
        h0r = n0r; h0i = n0i; h1r = n1r; h1i = n1i;
        __stcs((float2*)(op + (size_t)t * D), make_float2(h0r, h1r));
    }
}

extern "C" void kernel_launch(void* const* d_in, const int* in_sizes, int n_in,
                              void* d_out, int out_size) {
    const float* x    = (const float*)d_in[0];
    const float* p_re = (const float*)d_in[1];
    const float* p_im = (const float*)d_in[2];
    const float* i_re = (const float*)d_in[3];
    const float* i_im = (const float*)d_in[4];
    const float* lc_r = (const float*)d_in[5];
    const float* lc_i = (const float*)d_in[6];
    float* out = (float*)d_out;

    dim3 grid(1, NC, B);   // 512 blocks
    k1_totals<<<grid, 512>>>(x, p_re, p_im, i_re, i_im);
    k2_carries<<<(B * D) / 512, 512>>>(p_re, p_im, lc_r, lc_i);
    k3_scan<<<grid, 512>>>(x, p_re, p_im, i_re, i_im, out);
}